// round 16
// baseline (speedup 1.0000x reference)
#include <cuda_runtime.h>
#include <cuda_fp16.h>
#include <cstdint>

// ---------------------------------------------------------------------------
// NALU via fp16 mma.sync (m16n8k16), inverted fusion, 2-CTA/SM shape:
//   W = tanh(W_hat)*sigmoid(M_hat)
//   gemm_m : exp(L @ W) -> g_Mbh (fp16), 64-col tiles (2048 CTAs, ~no tail)
//   gemm_ag: a = x@W, g = x@gate together (B rows pair-interleaved W/gate,
//            32-row pairs), epilogue: out = sig(g)*a + (1-sig(g))*m_exp
// Block 128xBROWS, 4 warps (2x2), KT=64 SW128 swizzle, 3-stage cp.async,
// reg double-buffered frags, 128 thr, 2 CTAs/SM.
// Scratch only referenced in device code (GB300 ATS trap).
// ---------------------------------------------------------------------------

#define NALU_EPS 1e-7f
static const int BB = 8192, DIN = 2048, DOUT = 2048;

__device__ __half g_Xh [8192u * 2048u];  // fp16(x)            [M][K]
__device__ __half g_Lh [8192u * 2048u];  // fp16(log(|x|+eps)) [M][K]
__device__ __half g_WG [4096u * 2048u];  // [W^T ; gate^T]     [N2][K] k-contiguous
__device__ __half g_Mbh[8192u * 2048u];  // exp(L @ W) fp16

// ---------------------------------------------------------------------------
// PTX helpers
// ---------------------------------------------------------------------------
__device__ __forceinline__ void cp_async16(void* smem, const void* gmem)
{
    unsigned saddr = (unsigned)__cvta_generic_to_shared(smem);
    asm volatile("cp.async.cg.shared.global [%0], [%1], 16;\n"
                 :: "r"(saddr), "l"(gmem));
}
__device__ __forceinline__ void cp_commit()
{
    asm volatile("cp.async.commit_group;\n");
}
template <int N> __device__ __forceinline__ void cp_wait()
{
    asm volatile("cp.async.wait_group %0;\n" :: "n"(N));
}

__device__ __forceinline__ float fast_sigmoid(float v)
{
    return __fdividef(1.f, 1.f + __expf(-v));
}
__device__ __forceinline__ float fast_tanh(float v)
{
    return 1.f - __fdividef(2.f, 1.f + __expf(2.f * v));
}

// ---------------------------------------------------------------------------
// Prep kernels
// ---------------------------------------------------------------------------
__global__ void prep_x_kernel(const float* __restrict__ x, int n4)
{
    int i = blockIdx.x * blockDim.x + threadIdx.x;
    if (i < n4) {
        float4 v = ((const float4*)x)[i];
        __half2 x0 = __floats2half2_rn(v.x, v.y);
        __half2 x1 = __floats2half2_rn(v.z, v.w);
        __half2 l0 = __floats2half2_rn(__logf(fabsf(v.x) + NALU_EPS),
                                       __logf(fabsf(v.y) + NALU_EPS));
        __half2 l1 = __floats2half2_rn(__logf(fabsf(v.z) + NALU_EPS),
                                       __logf(fabsf(v.w) + NALU_EPS));
        uint2 xo, lo;
        xo.x = *(unsigned*)&x0; xo.y = *(unsigned*)&x1;
        lo.x = *(unsigned*)&l0; lo.y = *(unsigned*)&l1;
        ((uint2*)g_Xh)[i] = xo;
        ((uint2*)g_Lh)[i] = lo;
    }
}

__global__ void prep_wg_kernel(const float* __restrict__ Wh,
                               const float* __restrict__ Mh,
                               const float* __restrict__ gate)
{
    __shared__ __half tw[32][33];
    __shared__ __half tg_[32][33];
    const int kb = blockIdx.y * 32;
    const int nb = blockIdx.x * 32;
    const int tx = threadIdx.x, ty = threadIdx.y;

#pragma unroll
    for (int i = 0; i < 4; i++) {
        int k = kb + ty + i * 8;
        size_t idx = (size_t)k * 2048 + nb + tx;
        float w = Wh[idx], m = Mh[idx], gt = gate[idx];
        tw[ty + i * 8][tx]  = __float2half_rn(fast_tanh(w) * fast_sigmoid(m));
        tg_[ty + i * 8][tx] = __float2half_rn(gt);
    }
    __syncthreads();
#pragma unroll
    for (int i = 0; i < 4; i++) {
        int n = nb + ty + i * 8;
        g_WG[(size_t)n * 2048 + kb + tx]          = tw[tx][ty + i * 8];
        g_WG[(size_t)(2048 + n) * 2048 + kb + tx] = tg_[tx][ty + i * 8];
    }
}

// ---------------------------------------------------------------------------
// fp16 GEMM core: A-tile 128 rows, B-tile 16*NT rows, KT=64, SW128 swizzle,
// 4 warps 2x2 (warp tile 64 x NT*8), 3-stage cp.async, reg dbuf, 128 threads.
// MODE 1 (NT=8): B rows pair-interleaved W/gate for out cols [bnh, bnh+64);
//                epilogue combines acc-a (nt<4), acc-g (nt+4), g_Mbh.
// MODE 2 (NT=4): C_half = fp16(exp(A@B^T)), bn = blockIdx.x*64 B rows.
// ---------------------------------------------------------------------------
#define KT 64
#define A_TILE_B (128 * 128)             // 16 KB
#define NSTAGE 3
#define NKT 32                           // K / KT

template<int MODE, int NT>
__device__ __forceinline__ void gemm_f16_core(
    const __half* __restrict__ A, const __half* __restrict__ B,
    void* __restrict__ Cv)
{
    constexpr int B_TILE_B = 16 * NT * 128;       // bytes
    constexpr int STAGE_B  = A_TILE_B + B_TILE_B; // bytes

    extern __shared__ __half sm[];

    const int tid  = threadIdx.x;
    const int lane = tid & 31;
    const int warp = tid >> 5;           // 0..3
    const int wm   = (warp & 1) * 64;
    const int w2   = warp >> 1;          // 0..1
    const int wn   = w2 * (NT * 8);
    const int g    = lane >> 2;
    const int tg   = lane & 3;

    const int bm  = blockIdx.y * 128;
    const int bn  = blockIdx.x * 64;     // MODE 2: B-row base (W cols)
    const int bnh = blockIdx.x * 64;     // MODE 1: output-col base

    float acc[4][NT][4];
#pragma unroll
    for (int mt = 0; mt < 4; mt++)
#pragma unroll
        for (int nt = 0; nt < NT; nt++)
#pragma unroll
            for (int r = 0; r < 4; r++) acc[mt][nt][r] = 0.f;

    auto load_stage = [&](int kt, int s) {
        const int k0 = kt * KT;
        __half* as = sm + (size_t)s * (STAGE_B / 2);
        __half* bs = as + A_TILE_B / 2;
#pragma unroll
        for (int j = 0; j < 8; j++) {            // A: 1024 x 16B chunks
            const int idx = j * 128 + tid;
            const int r = idx >> 3, c = idx & 7;
            cp_async16(&as[r * 64 + ((c ^ (r & 7)) << 3)],
                       &A[(size_t)(bm + r) * 2048 + k0 + c * 8]);
        }
#pragma unroll
        for (int j = 0; j < NT; j++) {           // B: 128*NT x 16B chunks
            const int idx = j * 128 + tid;
            const int r = idx >> 3, c = idx & 7;
            int grow;
            if (MODE == 1) {
                const int pair = r >> 5;         // 0..3
                grow = ((pair & 1) << 11) + bnh + ((pair >> 1) << 5) + (r & 31);
            } else {
                grow = bn + r;
            }
            cp_async16(&bs[r * 64 + ((c ^ (r & 7)) << 3)],
                       &B[(size_t)grow * 2048 + k0 + c * 8]);
        }
    };

    load_stage(0, 0); cp_commit();
    load_stage(1, 1); cp_commit();

    unsigned a[2][4][4], b[2][NT][2];

    auto load_frags = [&](const __half* as, const __half* bs, int kbi, int p) {
        const int cs0 = ((2 * kbi) ^ g) << 3;
        const int cs1 = ((2 * kbi + 1) ^ g) << 3;
#pragma unroll
        for (int mt = 0; mt < 4; mt++) {
            const int r = (wm + mt * 16 + g) * 64 + 2 * tg;
            a[p][mt][0] = *(const unsigned*)&as[r + cs0];
            a[p][mt][1] = *(const unsigned*)&as[r + 8 * 64 + cs0];
            a[p][mt][2] = *(const unsigned*)&as[r + cs1];
            a[p][mt][3] = *(const unsigned*)&as[r + 8 * 64 + cs1];
        }
#pragma unroll
        for (int nt = 0; nt < NT; nt++) {
            const int rb = (wn + nt * 8 + g) * 64 + 2 * tg;
            b[p][nt][0] = *(const unsigned*)&bs[rb + cs0];
            b[p][nt][1] = *(const unsigned*)&bs[rb + cs1];
        }
    };

    auto mma_all = [&](int p) {
#pragma unroll
        for (int mt = 0; mt < 4; mt++)
#pragma unroll
            for (int nt = 0; nt < NT; nt++) {
                asm volatile(
                    "mma.sync.aligned.m16n8k16.row.col.f32.f16.f16.f32 "
                    "{%0,%1,%2,%3}, {%4,%5,%6,%7}, {%8,%9}, {%0,%1,%2,%3};\n"
                    : "+f"(acc[mt][nt][0]), "+f"(acc[mt][nt][1]),
                      "+f"(acc[mt][nt][2]), "+f"(acc[mt][nt][3])
                    : "r"(a[p][mt][0]), "r"(a[p][mt][1]),
                      "r"(a[p][mt][2]), "r"(a[p][mt][3]),
                      "r"(b[p][nt][0]), "r"(b[p][nt][1]));
            }
    };

    for (int kt = 0; kt < NKT; kt++) {
        cp_wait<1>();
        __syncthreads();

        const __half* as = sm + (size_t)(kt % NSTAGE) * (STAGE_B / 2);
        const __half* bs = as + A_TILE_B / 2;

        load_frags(as, bs, 0, 0);
#pragma unroll
        for (int kbi = 0; kbi < 4; kbi++) {
            if (kbi < 3) load_frags(as, bs, kbi + 1, (kbi + 1) & 1);
            mma_all(kbi & 1);
        }

        if (kt + 2 < NKT) load_stage(kt + 2, (kt + 2) % NSTAGE);
        cp_commit();
    }

    // ---- epilogue ----
    if (MODE == 1) {
        float* C = (float*)Cv;
        // acc[mt][nt] (nt<4) = a for out col c; acc[mt][nt+4] = g, same lane.
        // Software-pipelined g_Mbh loads: prefetch mt+1 while combining mt.
        __half2 mv[2][4][2];
        auto load_mv = [&](int mt, int p) {
            const int r0 = bm + wm + mt * 16 + g;
#pragma unroll
            for (int nt = 0; nt < 4; nt++) {
                const int c = bnh + w2 * 32 + nt * 8 + 2 * tg;
                mv[p][nt][0] = *(const __half2*)&g_Mbh[(size_t)r0 * 2048 + c];
                mv[p][nt][1] = *(const __half2*)&g_Mbh[(size_t)(r0 + 8) * 2048 + c];
            }
        };
        load_mv(0, 0);
#pragma unroll
        for (int mt = 0; mt < 4; mt++) {
            if (mt < 3) load_mv(mt + 1, (mt + 1) & 1);
            const int r0 = bm + wm + mt * 16 + g;
#pragma unroll
            for (int nt = 0; nt < 4; nt++) {
                const int c = bnh + w2 * 32 + nt * 8 + 2 * tg;
#pragma unroll
                for (int h = 0; h < 2; h++) {
                    const int r = r0 + 8 * h;
                    float2 m2 = __half22float2(mv[mt & 1][nt][h]);
                    float a0 = acc[mt][nt][2 * h], a1 = acc[mt][nt][2 * h + 1];
                    float g0 = acc[mt][nt + 4][2 * h], g1 = acc[mt][nt + 4][2 * h + 1];
                    float2 o;
                    {
                        float sg = fast_sigmoid(g0);
                        o.x = sg * a0 + (1.f - sg) * m2.x;
                    }
                    {
                        float sg = fast_sigmoid(g1);
                        o.y = sg * a1 + (1.f - sg) * m2.y;
                    }
                    *(float2*)&C[(size_t)r * 2048 + c] = o;
                }
            }
        }
    } else {
        // MODE 2: store fp16 exp(acc)
        __half* C = (__half*)Cv;
#pragma unroll
        for (int mt = 0; mt < 4; mt++) {
            const int r0 = bm + wm + mt * 16 + g;
#pragma unroll
            for (int nt = 0; nt < NT; nt++) {
                const int c = bn + wn + nt * 8 + 2 * tg;
#pragma unroll
                for (int h = 0; h < 2; h++) {
                    const int r = r0 + 8 * h;
                    __half2 hv = __floats2half2_rn(__expf(acc[mt][nt][2 * h]),
                                                   __expf(acc[mt][nt][2 * h + 1]));
                    *(__half2*)&C[(size_t)r * 2048 + c] = hv;
                }
            }
        }
    }
}

#define SMEM_M  (NSTAGE * (A_TILE_B + 16 * 4 * 128))   // 73728
#define SMEM_AG (NSTAGE * (A_TILE_B + 16 * 8 * 128))   // 98304

// Wrappers: scratch pointers formed IN DEVICE CODE (GB300 ATS trap).
__global__ __launch_bounds__(128, 2)
void gemm_m_kernel()
{
    gemm_f16_core<2, 4>(g_Lh, g_WG, g_Mbh);
}
__global__ __launch_bounds__(128, 2)
void gemm_ag_kernel(float* __restrict__ out)
{
    gemm_f16_core<1, 8>(g_Xh, g_WG, out);
}

// ---------------------------------------------------------------------------
// Launch
// ---------------------------------------------------------------------------
extern "C" void kernel_launch(void* const* d_in, const int* in_sizes, int n_in,
                              void* d_out, int out_size)
{
    const float* x    = (const float*)d_in[0];
    const float* Wh   = (const float*)d_in[1];
    const float* Mh   = (const float*)d_in[2];
    const float* gate = (const float*)d_in[3];
    float* out = (float*)d_out;

    static bool attr_set = false;
    if (!attr_set) {
        cudaFuncSetAttribute(gemm_m_kernel,
                             cudaFuncAttributeMaxDynamicSharedMemorySize, SMEM_M);
        cudaFuncSetAttribute(gemm_ag_kernel,
                             cudaFuncAttributeMaxDynamicSharedMemorySize, SMEM_AG);
        attr_set = true;
    }

    {
        int n4 = (BB * DIN) / 4;
        prep_x_kernel<<<(n4 + 255) / 256, 256>>>(x, n4);
    }
    {
        dim3 blk(32, 8), grd(DOUT / 32, DIN / 32);
        prep_wg_kernel<<<grd, blk>>>(Wh, Mh, gate);
    }

    {
        dim3 grid(2048 / 64, BB / 128);    // (32, 64) -> exp(L@W) fp16
        gemm_m_kernel<<<grid, 128, SMEM_M>>>();
    }
    {
        dim3 grid(2048 / 64, BB / 128);    // (32, 64) -> a,g + combine
        gemm_ag_kernel<<<grid, 128, SMEM_AG>>>(out);
    }
}

// round 17
// speedup vs baseline: 1.0609x; 1.0609x over previous
#include <cuda_runtime.h>
#include <cuda_fp16.h>
#include <cstdint>

// ---------------------------------------------------------------------------
// NALU via fp16 mma.sync (m16n8k16), inverted fusion, 2-CTA/SM shape:
//   W = tanh(W_hat)*sigmoid(M_hat)
//   gemm_m : exp(L @ W) -> g_Mbh (fp16), NT=8 tiles (R15 shape)
//   gemm_ag: a = x@W, g = x@gate together (B rows pair-interleaved W/gate,
//            32-row pairs), epilogue: out = sig(g)*a + (1-sig(g))*m_exp
// Block 128x128(b-rows), 4 warps (2x2, warp tile 64x64), KT=64 SW128 swizzle,
// 3-stage cp.async, reg double-buffered frags, 128 thr, 2 CTAs/SM.
// Scratch only referenced in device code (GB300 ATS trap).
// ---------------------------------------------------------------------------

#define NALU_EPS 1e-7f
static const int BB = 8192, DIN = 2048, DOUT = 2048;

__device__ __half g_Xh [8192u * 2048u];  // fp16(x)            [M][K]
__device__ __half g_Lh [8192u * 2048u];  // fp16(log(|x|+eps)) [M][K]
__device__ __half g_WG [4096u * 2048u];  // [W^T ; gate^T]     [N2][K] k-contiguous
__device__ __half g_Mbh[8192u * 2048u];  // exp(L @ W) fp16

// ---------------------------------------------------------------------------
// PTX helpers
// ---------------------------------------------------------------------------
__device__ __forceinline__ void cp_async16(void* smem, const void* gmem)
{
    unsigned saddr = (unsigned)__cvta_generic_to_shared(smem);
    asm volatile("cp.async.cg.shared.global [%0], [%1], 16;\n"
                 :: "r"(saddr), "l"(gmem));
}
__device__ __forceinline__ void cp_commit()
{
    asm volatile("cp.async.commit_group;\n");
}
template <int N> __device__ __forceinline__ void cp_wait()
{
    asm volatile("cp.async.wait_group %0;\n" :: "n"(N));
}

__device__ __forceinline__ float fast_sigmoid(float v)
{
    return __fdividef(1.f, 1.f + __expf(-v));
}
__device__ __forceinline__ float fast_tanh(float v)
{
    return 1.f - __fdividef(2.f, 1.f + __expf(2.f * v));
}

// ---------------------------------------------------------------------------
// Prep kernels
// ---------------------------------------------------------------------------
__global__ void prep_x_kernel(const float* __restrict__ x, int n4)
{
    int i = blockIdx.x * blockDim.x + threadIdx.x;
    if (i < n4) {
        float4 v = ((const float4*)x)[i];
        __half2 x0 = __floats2half2_rn(v.x, v.y);
        __half2 x1 = __floats2half2_rn(v.z, v.w);
        __half2 l0 = __floats2half2_rn(__logf(fabsf(v.x) + NALU_EPS),
                                       __logf(fabsf(v.y) + NALU_EPS));
        __half2 l1 = __floats2half2_rn(__logf(fabsf(v.z) + NALU_EPS),
                                       __logf(fabsf(v.w) + NALU_EPS));
        uint2 xo, lo;
        xo.x = *(unsigned*)&x0; xo.y = *(unsigned*)&x1;
        lo.x = *(unsigned*)&l0; lo.y = *(unsigned*)&l1;
        ((uint2*)g_Xh)[i] = xo;
        ((uint2*)g_Lh)[i] = lo;
    }
}

__global__ void prep_wg_kernel(const float* __restrict__ Wh,
                               const float* __restrict__ Mh,
                               const float* __restrict__ gate)
{
    __shared__ __half tw[32][33];
    __shared__ __half tg_[32][33];
    const int kb = blockIdx.y * 32;
    const int nb = blockIdx.x * 32;
    const int tx = threadIdx.x, ty = threadIdx.y;

#pragma unroll
    for (int i = 0; i < 4; i++) {
        int k = kb + ty + i * 8;
        size_t idx = (size_t)k * 2048 + nb + tx;
        float w = Wh[idx], m = Mh[idx], gt = gate[idx];
        tw[ty + i * 8][tx]  = __float2half_rn(fast_tanh(w) * fast_sigmoid(m));
        tg_[ty + i * 8][tx] = __float2half_rn(gt);
    }
    __syncthreads();
#pragma unroll
    for (int i = 0; i < 4; i++) {
        int n = nb + ty + i * 8;
        g_WG[(size_t)n * 2048 + kb + tx]          = tw[tx][ty + i * 8];
        g_WG[(size_t)(2048 + n) * 2048 + kb + tx] = tg_[tx][ty + i * 8];
    }
}

// ---------------------------------------------------------------------------
// fp16 GEMM core: A-tile 128 rows, B-tile 128 rows (NT=8), KT=64, SW128
// swizzle, 4 warps 2x2 (warp tile 64x64), 3-stage cp.async, reg dbuf.
// MODE 1: B rows pair-interleaved W/gate for out cols [bnh, bnh+64);
//         epilogue combines acc-a (nt<4), acc-g (nt+4), g_Mbh.
// MODE 2: C_half = fp16(exp(A@B^T)), bn = blockIdx.x*128 B rows.
// ---------------------------------------------------------------------------
#define KT 64
#define A_TILE_B (128 * 128)             // 16 KB
#define B_TILE_B (128 * 128)             // 16 KB
#define STAGE_B (A_TILE_B + B_TILE_B)    // 32 KB
#define NSTAGE 3
#define GEMM_SMEM (NSTAGE * STAGE_B)     // 98304
#define NKT 32                           // K / KT

template<int MODE>
__device__ __forceinline__ void gemm_f16_core(
    const __half* __restrict__ A, const __half* __restrict__ B,
    void* __restrict__ Cv)
{
    extern __shared__ __half sm[];

    const int tid  = threadIdx.x;
    const int lane = tid & 31;
    const int warp = tid >> 5;           // 0..3
    const int wm   = (warp & 1) * 64;
    const int w2   = warp >> 1;          // 0..1
    const int wn   = w2 * 64;
    const int g    = lane >> 2;
    const int tg   = lane & 3;

    const int bm  = blockIdx.y * 128;
    const int bn  = blockIdx.x * 128;    // MODE 2: B-row base
    const int bnh = blockIdx.x * 64;     // MODE 1: output-col base

    float acc[4][8][4];
#pragma unroll
    for (int mt = 0; mt < 4; mt++)
#pragma unroll
        for (int nt = 0; nt < 8; nt++)
#pragma unroll
            for (int r = 0; r < 4; r++) acc[mt][nt][r] = 0.f;

    auto load_stage = [&](int kt, int s) {
        const int k0 = kt * KT;
        __half* as = sm + (size_t)s * (STAGE_B / 2);
        __half* bs = as + A_TILE_B / 2;
#pragma unroll
        for (int j = 0; j < 8; j++) {            // A: 1024 x 16B chunks
            const int idx = j * 128 + tid;
            const int r = idx >> 3, c = idx & 7;
            cp_async16(&as[r * 64 + ((c ^ (r & 7)) << 3)],
                       &A[(size_t)(bm + r) * 2048 + k0 + c * 8]);
        }
#pragma unroll
        for (int j = 0; j < 8; j++) {            // B: 1024 x 16B chunks
            const int idx = j * 128 + tid;
            const int r = idx >> 3, c = idx & 7;
            int grow;
            if (MODE == 1) {
                const int pair = r >> 5;         // 0..3
                grow = ((pair & 1) << 11) + bnh + ((pair >> 1) << 5) + (r & 31);
            } else {
                grow = bn + r;
            }
            cp_async16(&bs[r * 64 + ((c ^ (r & 7)) << 3)],
                       &B[(size_t)grow * 2048 + k0 + c * 8]);
        }
    };

    load_stage(0, 0); cp_commit();
    load_stage(1, 1); cp_commit();

    unsigned a[2][4][4], b[2][8][2];

    auto load_frags = [&](const __half* as, const __half* bs, int kbi, int p) {
        const int cs0 = ((2 * kbi) ^ g) << 3;
        const int cs1 = ((2 * kbi + 1) ^ g) << 3;
#pragma unroll
        for (int mt = 0; mt < 4; mt++) {
            const int r = (wm + mt * 16 + g) * 64 + 2 * tg;
            a[p][mt][0] = *(const unsigned*)&as[r + cs0];
            a[p][mt][1] = *(const unsigned*)&as[r + 8 * 64 + cs0];
            a[p][mt][2] = *(const unsigned*)&as[r + cs1];
            a[p][mt][3] = *(const unsigned*)&as[r + 8 * 64 + cs1];
        }
#pragma unroll
        for (int nt = 0; nt < 8; nt++) {
            const int rb = (wn + nt * 8 + g) * 64 + 2 * tg;
            b[p][nt][0] = *(const unsigned*)&bs[rb + cs0];
            b[p][nt][1] = *(const unsigned*)&bs[rb + cs1];
        }
    };

    auto mma_all = [&](int p) {
#pragma unroll
        for (int mt = 0; mt < 4; mt++)
#pragma unroll
            for (int nt = 0; nt < 8; nt++) {
                asm volatile(
                    "mma.sync.aligned.m16n8k16.row.col.f32.f16.f16.f32 "
                    "{%0,%1,%2,%3}, {%4,%5,%6,%7}, {%8,%9}, {%0,%1,%2,%3};\n"
                    : "+f"(acc[mt][nt][0]), "+f"(acc[mt][nt][1]),
                      "+f"(acc[mt][nt][2]), "+f"(acc[mt][nt][3])
                    : "r"(a[p][mt][0]), "r"(a[p][mt][1]),
                      "r"(a[p][mt][2]), "r"(a[p][mt][3]),
                      "r"(b[p][nt][0]), "r"(b[p][nt][1]));
            }
    };

    for (int kt = 0; kt < NKT; kt++) {
        cp_wait<1>();
        __syncthreads();

        const __half* as = sm + (size_t)(kt % NSTAGE) * (STAGE_B / 2);
        const __half* bs = as + A_TILE_B / 2;

        load_frags(as, bs, 0, 0);
#pragma unroll
        for (int kbi = 0; kbi < 4; kbi++) {
            if (kbi < 3) load_frags(as, bs, kbi + 1, (kbi + 1) & 1);
            mma_all(kbi & 1);
        }

        if (kt + 2 < NKT) load_stage(kt + 2, (kt + 2) % NSTAGE);
        cp_commit();
    }

    // ---- epilogue ----
    if (MODE == 1) {
        float* C = (float*)Cv;
        // acc[mt][nt] (nt<4) = a for out col c; acc[mt][nt+4] = g, same lane.
        // Software-pipelined g_Mbh loads: prefetch mt+1 while combining mt.
        __half2 mv[2][4][2];
        auto load_mv = [&](int mt, int p) {
            const int r0 = bm + wm + mt * 16 + g;
#pragma unroll
            for (int nt = 0; nt < 4; nt++) {
                const int c = bnh + w2 * 32 + nt * 8 + 2 * tg;
                mv[p][nt][0] = *(const __half2*)&g_Mbh[(size_t)r0 * 2048 + c];
                mv[p][nt][1] = *(const __half2*)&g_Mbh[(size_t)(r0 + 8) * 2048 + c];
            }
        };
        load_mv(0, 0);
#pragma unroll
        for (int mt = 0; mt < 4; mt++) {
            if (mt < 3) load_mv(mt + 1, (mt + 1) & 1);
            const int r0 = bm + wm + mt * 16 + g;
#pragma unroll
            for (int nt = 0; nt < 4; nt++) {
                const int c = bnh + w2 * 32 + nt * 8 + 2 * tg;
#pragma unroll
                for (int h = 0; h < 2; h++) {
                    const int r = r0 + 8 * h;
                    float2 m2 = __half22float2(mv[mt & 1][nt][h]);
                    float a0 = acc[mt][nt][2 * h], a1 = acc[mt][nt][2 * h + 1];
                    float g0 = acc[mt][nt + 4][2 * h], g1 = acc[mt][nt + 4][2 * h + 1];
                    float2 o;
                    {
                        float sg = fast_sigmoid(g0);
                        o.x = sg * a0 + (1.f - sg) * m2.x;
                    }
                    {
                        float sg = fast_sigmoid(g1);
                        o.y = sg * a1 + (1.f - sg) * m2.y;
                    }
                    *(float2*)&C[(size_t)r * 2048 + c] = o;
                }
            }
        }
    } else {
        // MODE 2: store fp16 exp(acc)
        __half* C = (__half*)Cv;
#pragma unroll
        for (int mt = 0; mt < 4; mt++) {
            const int r0 = bm + wm + mt * 16 + g;
#pragma unroll
            for (int nt = 0; nt < 8; nt++) {
                const int c = bn + wn + nt * 8 + 2 * tg;
#pragma unroll
                for (int h = 0; h < 2; h++) {
                    const int r = r0 + 8 * h;
                    __half2 hv = __floats2half2_rn(__expf(acc[mt][nt][2 * h]),
                                                   __expf(acc[mt][nt][2 * h + 1]));
                    *(__half2*)&C[(size_t)r * 2048 + c] = hv;
                }
            }
        }
    }
}

// Wrappers: scratch pointers formed IN DEVICE CODE (GB300 ATS trap).
__global__ __launch_bounds__(128, 2)
void gemm_m_kernel()
{
    gemm_f16_core<2>(g_Lh, g_WG, g_Mbh);
}
__global__ __launch_bounds__(128, 2)
void gemm_ag_kernel(float* __restrict__ out)
{
    gemm_f16_core<1>(g_Xh, g_WG, out);
}

// ---------------------------------------------------------------------------
// Launch
// ---------------------------------------------------------------------------
extern "C" void kernel_launch(void* const* d_in, const int* in_sizes, int n_in,
                              void* d_out, int out_size)
{
    const float* x    = (const float*)d_in[0];
    const float* Wh   = (const float*)d_in[1];
    const float* Mh   = (const float*)d_in[2];
    const float* gate = (const float*)d_in[3];
    float* out = (float*)d_out;

    static bool attr_set = false;
    if (!attr_set) {
        cudaFuncSetAttribute(gemm_m_kernel,
                             cudaFuncAttributeMaxDynamicSharedMemorySize, GEMM_SMEM);
        cudaFuncSetAttribute(gemm_ag_kernel,
                             cudaFuncAttributeMaxDynamicSharedMemorySize, GEMM_SMEM);
        attr_set = true;
    }

    {
        int n4 = (BB * DIN) / 4;
        prep_x_kernel<<<(n4 + 255) / 256, 256>>>(x, n4);
    }
    {
        dim3 blk(32, 8), grd(DOUT / 32, DIN / 32);
        prep_wg_kernel<<<grd, blk>>>(Wh, Mh, gate);
    }

    {
        dim3 grid(2048 / 128, BB / 128);   // (16, 64) -> exp(L@W) fp16
        gemm_m_kernel<<<grid, 128, GEMM_SMEM>>>();
    }
    {
        dim3 grid(2048 / 64, BB / 128);    // (32, 64) -> a,g + combine
        gemm_ag_kernel<<<grid, 128, GEMM_SMEM>>>(out);
    }
}